// round 15
// baseline (speedup 1.0000x reference)
#include <cuda_runtime.h>
#include <cuda_bf16.h>
#include <math.h>
#include <stdint.h>
#include <stddef.h>

#define BDIM 128
#define TDIM 512
#define IDIM 32
#define HDIM 1024
#define GDIM 4096
#define BH   (BDIM*HDIM)
#define NBLK 128
#define NTHR 1024           // 4 K-groups x 8 warps
#define MSZ  4194304        // 4096*1024 elements per weight matrix
#define WREC 1048576        // uint4 records per weight matrix (MSZ/4)
#define HREC 32768          // uint4 records per H buffer (128*1024/4)

// weight slots in the packed store
#define W_EWH0 0
#define W_EWH1 1
#define W_EWH2 2
#define W_DWH0 3
#define W_DWI1 4
#define W_DWI2 5
#define W_DWH1 6
#define W_DWH2 7
#define W_HWI1 8
#define W_HWI2 9
#define NWMAT  10

// ---------------- static device scratch (no allocations anywhere) ----------------
// Packed record layout (16 B per lane-record = 4 elements' hi+lo):
//   bf16[0..1]=hi k-tile t0, bf16[2..3]=hi t1, bf16[4..5]=lo t0, bf16[6..7]=lo t1
static __device__ uint4 g_w4[(size_t)NWMAT * WREC];          // packed weights (160 MB)
static __device__ uint4 g_eh4[2][HREC];                      // encoder h ping-pong
static __device__ uint4 g_z4[HREC];                          // never written -> zeros
static __device__ uint4 g_dh4[2][3][HREC];                   // decoder h [par][layer]
static __device__ uint4 g_s4[(size_t)TDIM * HREC];           // seq acts, slab-per-t (256 MB)
static __device__ float g_h2f[BH];                           // decoder top-layer h [u][b] (head)
static __device__ float g_xg[(size_t)TDIM * GDIM * BDIM];    // input-gate preacts [t][g][u][b] (1 GB)
static __device__ float g_cT[3 * BH];                        // encoder final c
static __device__ float g_xfeed[BDIM];
static __device__ unsigned g_count = 0;
static __device__ unsigned g_gen = 0;

// xg address: [t][gate q][unit u][batch b]  -> lane-consecutive in b
__device__ __forceinline__ size_t XG(int t, int q, int u, int b) {
    return ((((size_t)t << 12) + ((size_t)q << 10) + (size_t)u) << 7) + (size_t)b;
}

// ---------------- software grid barrier (all NBLK blocks resident) ----------------
__device__ __forceinline__ void gsync() {
    __syncthreads();
    if (threadIdx.x == 0) {
        unsigned gen = *((volatile unsigned*)&g_gen);
        __threadfence();
        if (atomicAdd(&g_count, 1u) == gridDim.x - 1) {
            atomicExch(&g_count, 0u);
            __threadfence();
            *((volatile unsigned*)&g_gen) = gen + 1u;
        } else {
            while (*((volatile unsigned*)&g_gen) == gen) __nanosleep(32);
        }
        __threadfence();
    }
    __syncthreads();
}

__device__ __forceinline__ float sigm(float x) { return 1.f / (1.f + expf(-x)); }

#define MMA16816(C, A0, A1, A2, A3, B0, B1) \
    asm volatile("mma.sync.aligned.m16n8k16.row.col.f32.bf16.bf16.f32 " \
        "{%0,%1,%2,%3}, {%4,%5,%6,%7}, {%8,%9}, {%0,%1,%2,%3};" \
        : "+f"((C)[0]), "+f"((C)[1]), "+f"((C)[2]), "+f"((C)[3]) \
        : "r"(A0), "r"(A1), "r"(A2), "r"(A3), "r"(B0), "r"(B1))

// write one fp32 value as packed hi/lo bf16 into an H-style record array
__device__ __forceinline__ void put_h(uint4* H4, int b, int u, float hn) {
    __nv_bfloat16 hh = __float2bfloat16(hn);
    __nv_bfloat16 hl = __float2bfloat16(hn - __bfloat162float(hh));
    const int t01 = (u >> 3) & 1, half = u & 1;
    __nv_bfloat16* p = (__nv_bfloat16*)(H4 + ((size_t)((b >> 3) * 64 + (u >> 4)) * 32
                                              + (b & 7) * 4 + ((u & 7) >> 1)));
    p[t01 * 2 + half]     = hh;
    p[4 + t01 * 2 + half] = hl;
}

// ---------------- weight prep: fp32 -> packed hi/lo records ----------------
__global__ void prep_w(const float* p0, const float* p1, const float* p2, const float* p3,
                       const float* p4, const float* p5, const float* p6, const float* p7,
                       const float* p8, const float* p9)
{
    for (size_t i = (size_t)blockIdx.x * blockDim.x + threadIdx.x;
         i < (size_t)NWMAT * MSZ; i += (size_t)gridDim.x * blockDim.x) {
        int m = (int)(i >> 22);
        int e = (int)(i & (MSZ - 1));
        const float* src;
        switch (m) {
            case 0: src = p0; break; case 1: src = p1; break;
            case 2: src = p2; break; case 3: src = p3; break;
            case 4: src = p4; break; case 5: src = p5; break;
            case 6: src = p6; break; case 7: src = p7; break;
            case 8: src = p8; break; default: src = p9; break;
        }
        float v = src[e];
        __nv_bfloat16 h = __float2bfloat16(v);
        __nv_bfloat16 l = __float2bfloat16(v - __bfloat162float(h));
        int row = e >> 10, k = e & 1023;
        uint4* rec = g_w4 + (size_t)m * WREC
                   + ((size_t)((row >> 3) * 64 + (k >> 4)) * 32
                      + (row & 7) * 4 + ((k & 7) >> 1));
        __nv_bfloat16* p = (__nv_bfloat16*)rec;
        const int t01 = (k >> 3) & 1, half = k & 1;
        p[t01 * 2 + half]     = h;
        p[4 + t01 * 2 + half] = l;
    }
}

// ---------------- block MMA over one K-quarter: C[32 Wrows, 128 rows] += W @ H^T ----------------
__device__ __forceinline__ void accum_mma(
    const uint4* __restrict__ W4, const uint4* __restrict__ H4,
    float C[4][4], int u0, int kg)
{
    const int tid = threadIdx.x;
    const int w8 = (tid >> 5) & 7, lane = tid & 31;
    const int q0 = (w8 & 1) * 2, q1 = q0 + 1;
    const uint32_t rb0 = (uint32_t)(q0 * 128 + (u0 >> 3)) * 2048u + (uint32_t)lane;
    const uint32_t rb1 = (uint32_t)(q1 * 128 + (u0 >> 3)) * 2048u + (uint32_t)lane;
    uint32_t hb[4];
#pragma unroll
    for (int j = 0; j < 4; j++)
        hb[j] = (uint32_t)((w8 >> 1) * 4 + j) * 2048u + (uint32_t)lane;

#pragma unroll 4
    for (int kt2 = 0; kt2 < 16; kt2++) {
        const uint32_t ko = (uint32_t)(kg * 16 + kt2) * 32u;
        uint4 wa = W4[rb0 + ko];     // A frags gate q0
        uint4 wb = W4[rb1 + ko];     // A frags gate q1
#pragma unroll
        for (int j = 0; j < 4; j++) {
            uint4 h = H4[hb[j] + ko];
            MMA16816(C[j], wa.x, wb.x, wa.y, wb.y, h.x, h.y);  // hi*hi
            MMA16816(C[j], wa.x, wb.x, wa.y, wb.y, h.z, h.w);  // hi*lo
            MMA16816(C[j], wa.z, wb.z, wa.w, wb.w, h.x, h.y);  // lo*hi
        }
    }
}

// store C fragments into gates smem [r_local 32][row 128]; r_local = q*8 + unit_off
__device__ __forceinline__ void store_C(float C[4][4], float (*gs)[132])
{
    const int tid = threadIdx.x;
    const int w8 = (tid >> 5) & 7, lane = tid & 31;
    const int g = lane >> 2, tg = lane & 3;
    const int r0 = (w8 & 1) * 16 + g;
    const int r1 = r0 + 8;
#pragma unroll
    for (int j = 0; j < 4; j++) {
        const int cb = (w8 >> 1) * 32 + j * 8 + 2 * tg;
        gs[r0][cb]     = C[j][0];
        gs[r0][cb + 1] = C[j][1];
        gs[r1][cb]     = C[j][2];
        gs[r1][cb + 1] = C[j][3];
    }
}

// add C fragments into gates smem (same owning threads as store_C -> race-free)
__device__ __forceinline__ void store_C_add(float C[4][4], float (*gs)[132])
{
    const int tid = threadIdx.x;
    const int w8 = (tid >> 5) & 7, lane = tid & 31;
    const int g = lane >> 2, tg = lane & 3;
    const int r0 = (w8 & 1) * 16 + g;
    const int r1 = r0 + 8;
#pragma unroll
    for (int j = 0; j < 4; j++) {
        const int cb = (w8 >> 1) * 32 + j * 8 + 2 * tg;
        gs[r0][cb]     += C[j][0];
        gs[r0][cb + 1] += C[j][1];
        gs[r1][cb]     += C[j][2];
        gs[r1][cb + 1] += C[j][3];
    }
}

// reduce 4 kg partials into 2 smem buffers (kg0/1 store, kg2/3 add)
__device__ __forceinline__ void reduce_C(float C[4][4], float (*gs01)[132],
                                         float (*gs23)[132], int kg)
{
    if (kg < 2) store_C(C, kg ? gs23 : gs01);
    __syncthreads();
    if (kg >= 2) store_C_add(C, (kg == 3) ? gs23 : gs01);
    __syncthreads();
}

// ---------------- bf16 MMA hoist GEMM: xg[t-slab] = W @ Sact[t-slab]^T ----------------
__global__ void __launch_bounds__(256, 2) hoist_mma(int wslot)
{
    __shared__ float gates_s[32][132];
    const int u0 = blockIdx.x * 8;
    const int t = blockIdx.y;

    float C[4][4];
#pragma unroll
    for (int a = 0; a < 4; a++)
#pragma unroll
        for (int b = 0; b < 4; b++) C[a][b] = 0.f;

#pragma unroll
    for (int kg = 0; kg < 4; kg++)
        accum_mma(g_w4 + (size_t)wslot * WREC, g_s4 + (size_t)t * HREC, C, u0, kg);
    store_C(C, gates_s);
    __syncthreads();

    const int tid = threadIdx.x;
#pragma unroll
    for (int pass = 0; pass < 16; pass++) {
        const int idx = pass * 256 + tid;
        const int b = idx & 127, r = idx >> 7;       // r = q*8 + uo
        g_xg[XG(t, r >> 3, u0 + (r & 7), b)] = gates_s[r][b];
    }
}

// ---------------- persistent encoder layer ----------------
__global__ void __launch_bounds__(NTHR, 1) enc_layer_kernel(
    int wslot, int dslot,
    const float* __restrict__ bih, const float* __restrict__ bhh,
    int write_seq)
{
    __shared__ float gs01[32][132];
    __shared__ float gs23[32][132];
    const int tid = threadIdx.x;
    const int u0 = blockIdx.x * 8;
    const int kg = tid >> 8;
    const int je = tid >> 7, be = tid & 127;   // epilogue cell: unit offset, batch
    const int ue = u0 + je;
    const uint4* W4 = g_w4 + (size_t)wslot * WREC;

    float bs[4];
#pragma unroll
    for (int q = 0; q < 4; q++) bs[q] = bih[(q << 10) + ue] + bhh[(q << 10) + ue];

    float cl = 0.f, hl = 0.f;

#pragma unroll 1
    for (int t = 0; t < TDIM; t++) {
        float C[4][4];
#pragma unroll
        for (int a = 0; a < 4; a++)
#pragma unroll
            for (int b = 0; b < 4; b++) C[a][b] = 0.f;

        const uint4* H = t ? g_eh4[t & 1] : g_z4;
        accum_mma(W4, H, C, u0, kg);
        reduce_C(C, gs01, gs23, kg);

        const int wp = (t + 1) & 1;
        {
            float ip = gs01[je][be]      + gs23[je][be]      + g_xg[XG(t, 0, ue, be)] + bs[0];
            float fp = gs01[8 + je][be]  + gs23[8 + je][be]  + g_xg[XG(t, 1, ue, be)] + bs[1];
            float gp = gs01[16 + je][be] + gs23[16 + je][be] + g_xg[XG(t, 2, ue, be)] + bs[2];
            float op = gs01[24 + je][be] + gs23[24 + je][be] + g_xg[XG(t, 3, ue, be)] + bs[3];
            float cn = sigm(fp) * cl + sigm(ip) * tanhf(gp);
            float hn = sigm(op) * tanhf(cn);
            cl = cn; hl = hn;
            put_h(g_eh4[wp], be, ue, hn);
            if (write_seq)
                put_h(g_s4 + (size_t)t * HREC, be, ue, hn);
        }
        gsync();
    }
    // export final states for the decoder
    g_cT[dslot * BH + be * HDIM + ue] = cl;
    put_h(&g_dh4[0][dslot][0], be, ue, hl);
}

// ---------------- persistent decoder ----------------
__global__ void __launch_bounds__(NTHR, 1) dec_kernel(
    const float* __restrict__ dWih0,
    const float* __restrict__ dbih0, const float* __restrict__ dbhh0,
    const float* __restrict__ dbih,  const float* __restrict__ dbhh,
    const float* __restrict__ Wu,    const float* __restrict__ bu,
    const float* __restrict__ y,     const int* __restrict__ force,
    float* __restrict__ out)
{
    __shared__ float gs01[32][132];
    __shared__ float gs23[32][132];
    __shared__ float red2[32];
    const int tid = threadIdx.x;
    const int u0 = blockIdx.x * 8;
    const int kg = tid >> 8;
    const int je = tid >> 7, be = tid & 127;
    const int ue = u0 + je;

    float bs0[4], bs1[4], bs2[4], wc0[4];
#pragma unroll
    for (int q = 0; q < 4; q++) {
        const int g = (q << 10) + ue;
        bs0[q] = dbih0[g] + dbhh0[g];
        bs1[q] = dbih[g] + dbhh[g];
        bs2[q] = dbih[GDIM + g] + dbhh[GDIM + g];
        wc0[q] = dWih0[g];
    }
    float c0 = g_cT[0 * BH + be * HDIM + ue];
    float c1 = g_cT[1 * BH + be * HDIM + ue];
    float c2 = g_cT[2 * BH + be * HDIM + ue];

    if (blockIdx.x == 0 && tid < BDIM) {
        g_xfeed[tid] = y[(size_t)tid * TDIM];
        out[(size_t)tid * TDIM] = 0.f;     // output[:,0] = 0
    }
    gsync();

#pragma unroll 1
    for (int s = 0; s < TDIM - 1; s++) {
        const int p = s & 1;
        float C[4][4];

        // ----- layer 0: gates = h0 @ Whh0^T (+ xfeed*Wih0 + b) -----
#pragma unroll
        for (int a = 0; a < 4; a++)
#pragma unroll
            for (int b = 0; b < 4; b++) C[a][b] = 0.f;
        accum_mma(g_w4 + (size_t)W_DWH0 * WREC, &g_dh4[p][0][0], C, u0, kg);
        reduce_C(C, gs01, gs23, kg);
        {
            const float xf = g_xfeed[be];
            float ip = gs01[je][be]      + gs23[je][be]      + xf * wc0[0] + bs0[0];
            float fp = gs01[8 + je][be]  + gs23[8 + je][be]  + xf * wc0[1] + bs0[1];
            float gp = gs01[16 + je][be] + gs23[16 + je][be] + xf * wc0[2] + bs0[2];
            float op = gs01[24 + je][be] + gs23[24 + je][be] + xf * wc0[3] + bs0[3];
            float cn = sigm(fp) * c0 + sigm(ip) * tanhf(gp);
            float hn = sigm(op) * tanhf(cn);
            c0 = cn;
            put_h(&g_dh4[p ^ 1][0][0], be, ue, hn);
        }
        gsync();

        // ----- layer 1: gates = h0_new @ Wih1^T + h1 @ Whh1^T -----
#pragma unroll
        for (int a = 0; a < 4; a++)
#pragma unroll
            for (int b = 0; b < 4; b++) C[a][b] = 0.f;
        accum_mma(g_w4 + (size_t)W_DWI1 * WREC, &g_dh4[p ^ 1][0][0], C, u0, kg);
        accum_mma(g_w4 + (size_t)W_DWH1 * WREC, &g_dh4[p][1][0], C, u0, kg);
        reduce_C(C, gs01, gs23, kg);
        {
            float ip = gs01[je][be]      + gs23[je][be]      + bs1[0];
            float fp = gs01[8 + je][be]  + gs23[8 + je][be]  + bs1[1];
            float gp = gs01[16 + je][be] + gs23[16 + je][be] + bs1[2];
            float op = gs01[24 + je][be] + gs23[24 + je][be] + bs1[3];
            float cn = sigm(fp) * c1 + sigm(ip) * tanhf(gp);
            float hn = sigm(op) * tanhf(cn);
            c1 = cn;
            put_h(&g_dh4[p ^ 1][1][0], be, ue, hn);
        }
        gsync();

        // ----- layer 2 -----
#pragma unroll
        for (int a = 0; a < 4; a++)
#pragma unroll
            for (int b = 0; b < 4; b++) C[a][b] = 0.f;
        accum_mma(g_w4 + (size_t)W_DWI2 * WREC, &g_dh4[p ^ 1][1][0], C, u0, kg);
        accum_mma(g_w4 + (size_t)W_DWH2 * WREC, &g_dh4[p][2][0], C, u0, kg);
        reduce_C(C, gs01, gs23, kg);
        {
            float ip = gs01[je][be]      + gs23[je][be]      + bs2[0];
            float fp = gs01[8 + je][be]  + gs23[8 + je][be]  + bs2[1];
            float gp = gs01[16 + je][be] + gs23[16 + je][be] + bs2[2];
            float op = gs01[24 + je][be] + gs23[24 + je][be] + bs2[3];
            float cn = sigm(fp) * c2 + sigm(ip) * tanhf(gp);
            float hn = sigm(op) * tanhf(cn);
            c2 = cn;
            g_h2f[ue * BDIM + be] = hn;           // [u][b] -> coalesced store
            put_h(&g_dh4[p ^ 1][2][0], be, ue, hn);
        }
        gsync();

        // ----- output head + teacher forcing: block b handles batch row b -----
        {
            // h2f[u][b]: lane k reads u=tid (one element per thread)
            float a = g_h2f[tid * BDIM + blockIdx.x] * Wu[tid];
#pragma unroll
            for (int o = 16; o; o >>= 1) a += __shfl_xor_sync(0xFFFFFFFFu, a, o);
            if ((tid & 31) == 0) red2[tid >> 5] = a;
            __syncthreads();
            if (tid == 0) {
                float ov = bu[0];
#pragma unroll
                for (int ww = 0; ww < 32; ww++) ov += red2[ww];
                out[(size_t)blockIdx.x * TDIM + s + 1] = ov;
                g_xfeed[blockIdx.x] = (force[s] > 0) ? y[(size_t)blockIdx.x * TDIM + s + 1] : ov;
            }
        }
        gsync();
    }
}

// ---------------- fp32 NT GEMM for the tiny K=32 layer-0 hoist ----------------
// writes xg in [t][q][u][b] layout
__global__ void __launch_bounds__(256) gemm_hoist(
    const float* __restrict__ A, const float* __restrict__ B, int K)
{
    __shared__ float As[16][68];
    __shared__ float Bs[16][68];
    const int tid = threadIdx.x;
    const int tx = tid & 15, ty = tid >> 4;
    const int m0 = blockIdx.y * 64, n0 = blockIdx.x * 64;
    const int lr = tid >> 2;
    const int lc = (tid & 3) * 4;

    float acc[4][4];
#pragma unroll
    for (int i = 0; i < 4; i++)
#pragma unroll
        for (int jj = 0; jj < 4; jj++) acc[i][jj] = 0.f;

#pragma unroll 1
    for (int k0 = 0; k0 < K; k0 += 16) {
        float4 av = *(const float4*)&A[(size_t)(m0 + lr) * K + k0 + lc];
        float4 bv = *(const float4*)&B[(size_t)(n0 + lr) * K + k0 + lc];
        __syncthreads();
        As[lc + 0][lr] = av.x; As[lc + 1][lr] = av.y; As[lc + 2][lr] = av.z; As[lc + 3][lr] = av.w;
        Bs[lc + 0][lr] = bv.x; Bs[lc + 1][lr] = bv.y; Bs[lc + 2][lr] = bv.z; Bs[lc + 3][lr] = bv.w;
        __syncthreads();
#pragma unroll
        for (int k = 0; k < 16; k++) {
            float4 a = *(const float4*)&As[k][ty * 4];
            float4 b = *(const float4*)&Bs[k][tx * 4];
            acc[0][0] += a.x * b.x; acc[0][1] += a.x * b.y; acc[0][2] += a.x * b.z; acc[0][3] += a.x * b.w;
            acc[1][0] += a.y * b.x; acc[1][1] += a.y * b.y; acc[1][2] += a.y * b.z; acc[1][3] += a.y * b.w;
            acc[2][0] += a.z * b.x; acc[2][1] += a.z * b.y; acc[2][2] += a.z * b.z; acc[2][3] += a.z * b.w;
            acc[3][0] += a.w * b.x; acc[3][1] += a.w * b.y; acc[3][2] += a.w * b.z; acc[3][3] += a.w * b.w;
        }
    }
#pragma unroll
    for (int i = 0; i < 4; i++) {
        const int m = m0 + ty * 4 + i;               // m = b*TDIM + t
        const int bb = m >> 9, t = m & 511;
#pragma unroll
        for (int jj = 0; jj < 4; jj++) {
            const int n = n0 + tx * 4 + jj;          // n = q*1024 + u
            g_xg[XG(t, n >> 10, n & 1023, bb)] = acc[i][jj];
        }
    }
}

// ---------------- host orchestration: 8 graph nodes ----------------
extern "C" void kernel_launch(void* const* d_in, const int* in_sizes, int n_in,
                              void* d_out, int out_size)
{
    (void)in_sizes; (void)n_in; (void)out_size;

    const float* x     = (const float*)d_in[0];
    const float* y     = (const float*)d_in[1];
    const int*   force = (const int*)  d_in[2];
    const float* eWih0 = (const float*)d_in[3];
    const float* eWhh0 = (const float*)d_in[4];
    const float* ebih0 = (const float*)d_in[5];
    const float* ebhh0 = (const float*)d_in[6];
    const float* eWih  = (const float*)d_in[7];
    const float* eWhh  = (const float*)d_in[8];
    const float* ebih  = (const float*)d_in[9];
    const float* ebhh  = (const float*)d_in[10];
    const float* dWih0 = (const float*)d_in[11];
    const float* dWhh0 = (const float*)d_in[12];
    const float* dbih0 = (const float*)d_in[13];
    const float* dbhh0 = (const float*)d_in[14];
    const float* dWih  = (const float*)d_in[15];
    const float* dWhh  = (const float*)d_in[16];
    const float* dbih  = (const float*)d_in[17];
    const float* dbhh  = (const float*)d_in[18];
    const float* Wu    = (const float*)d_in[19];
    const float* bu    = (const float*)d_in[20];
    float* out = (float*)d_out;

    const size_t WSTRIDE = (size_t)GDIM * HDIM;
    const dim3 gBig(GDIM / 64, (BDIM * TDIM) / 64);
    const dim3 gHoist(HDIM / 8, TDIM);

    // split all recurrent + hoist weights into packed bf16 hi/lo records
    prep_w<<<2048, 256>>>(eWhh0, eWhh, eWhh + WSTRIDE,
                          dWhh0, dWih, dWih + WSTRIDE,
                          dWhh, dWhh + WSTRIDE,
                          eWih, eWih + WSTRIDE);

    // encoder layer 0 (input hoist is tiny K=32 fp32 GEMM)
    gemm_hoist<<<gBig, 256>>>(x, eWih0, IDIM);
    enc_layer_kernel<<<NBLK, NTHR>>>(W_EWH0, 0, ebih0, ebhh0, /*write_seq=*/1);
    // encoder layer 1
    hoist_mma<<<gHoist, 256>>>(W_HWI1);
    enc_layer_kernel<<<NBLK, NTHR>>>(W_EWH1, 1, ebih, ebhh, /*write_seq=*/1);
    // encoder layer 2
    hoist_mma<<<gHoist, 256>>>(W_HWI2);
    enc_layer_kernel<<<NBLK, NTHR>>>(W_EWH2, 2, ebih + GDIM, ebhh + GDIM, /*write_seq=*/0);

    // decoder (persistent, all 511 steps)
    dec_kernel<<<NBLK, NTHR>>>(dWih0, dbih0, dbhh0, dbih, dbhh,
                               Wu, bu, y, force, out);
}

// round 16
// speedup vs baseline: 1.0872x; 1.0872x over previous
#include <cuda_runtime.h>
#include <cuda_bf16.h>
#include <math.h>
#include <stdint.h>
#include <stddef.h>

#define BDIM 128
#define TDIM 512
#define IDIM 32
#define HDIM 1024
#define GDIM 4096
#define BH   (BDIM*HDIM)
#define NBLK 128
#define NTHR 512            // 4 K-groups x 4 warps (m32n32 tiles)
#define MSZ  4194304        // 4096*1024 elements per weight matrix
#define WREC 1048576        // uint4 records per weight matrix (MSZ/4)
#define HREC 32768          // uint4 records per H buffer (128*1024/4)

// weight slots in the packed store
#define W_EWH0 0
#define W_EWH1 1
#define W_EWH2 2
#define W_DWH0 3
#define W_DWI1 4
#define W_DWI2 5
#define W_DWH1 6
#define W_DWH2 7
#define W_HWI1 8
#define W_HWI2 9
#define NWMAT  10

// ---------------- static device scratch (no allocations anywhere) ----------------
static __device__ uint4 g_w4[(size_t)NWMAT * WREC];          // packed weights (160 MB)
static __device__ uint4 g_eh4[2][HREC];                      // encoder h ping-pong
static __device__ uint4 g_z4[HREC];                          // never written -> zeros
static __device__ uint4 g_dh4[2][3][HREC];                   // decoder h [par][layer]
static __device__ uint4 g_s4[(size_t)TDIM * HREC];           // seq acts, slab-per-t (256 MB)
static __device__ float g_xg[(size_t)TDIM * GDIM * BDIM];    // input-gate preacts [t][g][u][b] (1 GB)
static __device__ float g_cT[3 * BH];                        // encoder final c
static __device__ float g_hacc[2][BDIM];                     // head partial sums (double buffer)
static __device__ unsigned g_count = 0;
static __device__ unsigned g_gen = 0;

// xg address: [t][gate q][unit u][batch b]  -> lane-consecutive in b
__device__ __forceinline__ size_t XG(int t, int q, int u, int b) {
    return ((((size_t)t << 12) + ((size_t)q << 10) + (size_t)u) << 7) + (size_t)b;
}

// ---------------- software grid barrier (all NBLK blocks resident) ----------------
__device__ __forceinline__ void gsync() {
    __syncthreads();
    if (threadIdx.x == 0) {
        unsigned gen = *((volatile unsigned*)&g_gen);
        __threadfence();
        if (atomicAdd(&g_count, 1u) == gridDim.x - 1) {
            atomicExch(&g_count, 0u);
            __threadfence();
            *((volatile unsigned*)&g_gen) = gen + 1u;
        } else {
            while (*((volatile unsigned*)&g_gen) == gen) __nanosleep(32);
        }
        __threadfence();
    }
    __syncthreads();
}

__device__ __forceinline__ float sigm(float x) { return 1.f / (1.f + expf(-x)); }

#define MMA16816(C, A0, A1, A2, A3, B0, B1) \
    asm volatile("mma.sync.aligned.m16n8k16.row.col.f32.bf16.bf16.f32 " \
        "{%0,%1,%2,%3}, {%4,%5,%6,%7}, {%8,%9}, {%0,%1,%2,%3};" \
        : "+f"((C)[0]), "+f"((C)[1]), "+f"((C)[2]), "+f"((C)[3]) \
        : "r"(A0), "r"(A1), "r"(A2), "r"(A3), "r"(B0), "r"(B1))

// write one fp32 value as packed hi/lo bf16 into an H-style record array
__device__ __forceinline__ void put_h(uint4* H4, int b, int u, float hn) {
    __nv_bfloat16 hh = __float2bfloat16(hn);
    __nv_bfloat16 hl = __float2bfloat16(hn - __bfloat162float(hh));
    const int t01 = (u >> 3) & 1, half = u & 1;
    __nv_bfloat16* p = (__nv_bfloat16*)(H4 + ((size_t)((b >> 3) * 64 + (u >> 4)) * 32
                                              + (b & 7) * 4 + ((u & 7) >> 1)));
    p[t01 * 2 + half]     = hh;
    p[4 + t01 * 2 + half] = hl;
}

// ---------------- weight prep: fp32 -> packed hi/lo records ----------------
__global__ void prep_w(const float* p0, const float* p1, const float* p2, const float* p3,
                       const float* p4, const float* p5, const float* p6, const float* p7,
                       const float* p8, const float* p9)
{
    for (size_t i = (size_t)blockIdx.x * blockDim.x + threadIdx.x;
         i < (size_t)NWMAT * MSZ; i += (size_t)gridDim.x * blockDim.x) {
        int m = (int)(i >> 22);
        int e = (int)(i & (MSZ - 1));
        const float* src;
        switch (m) {
            case 0: src = p0; break; case 1: src = p1; break;
            case 2: src = p2; break; case 3: src = p3; break;
            case 4: src = p4; break; case 5: src = p5; break;
            case 6: src = p6; break; case 7: src = p7; break;
            case 8: src = p8; break; default: src = p9; break;
        }
        float v = src[e];
        __nv_bfloat16 h = __float2bfloat16(v);
        __nv_bfloat16 l = __float2bfloat16(v - __bfloat162float(h));
        int row = e >> 10, k = e & 1023;
        uint4* rec = g_w4 + (size_t)m * WREC
                   + ((size_t)((row >> 3) * 64 + (k >> 4)) * 32
                      + (row & 7) * 4 + ((k & 7) >> 1));
        __nv_bfloat16* p = (__nv_bfloat16*)rec;
        const int t01 = (k >> 3) & 1, half = k & 1;
        p[t01 * 2 + half]     = h;
        p[4 + t01 * 2 + half] = l;
    }
}

// ---------------- warp m32n32 block MMA over one K-slice ----------------
// Each warp: all 32 W rows (4 gates x 8 units) x its n32 batch tile, K-range kg.
__device__ __forceinline__ void accum_m32(
    const uint4* __restrict__ W4, const uint4* __restrict__ H4,
    float C[2][4][4], int u0, int kg, int niter)
{
    const int tid = threadIdx.x;
    const int w4 = (tid >> 5) & 3;
    const int lane = tid & 31;
    uint32_t wb[4], hb[4];
#pragma unroll
    for (int q = 0; q < 4; q++)
        wb[q] = (uint32_t)(q * 128 + (u0 >> 3)) * 2048u + (uint32_t)lane;
#pragma unroll
    for (int j = 0; j < 4; j++)
        hb[j] = (uint32_t)(w4 * 4 + j) * 2048u + (uint32_t)lane;

#pragma unroll 4
    for (int it = 0; it < niter; it++) {
        const uint32_t ko = (uint32_t)(kg * niter + it) * 32u;
        uint4 a0 = W4[wb[0] + ko];
        uint4 a1 = W4[wb[1] + ko];
        uint4 a2 = W4[wb[2] + ko];
        uint4 a3 = W4[wb[3] + ko];
#pragma unroll
        for (int j = 0; j < 4; j++) {
            uint4 h = H4[hb[j] + ko];
            MMA16816(C[0][j], a0.x, a1.x, a0.y, a1.y, h.x, h.y);  // hi*hi (gates 0,1)
            MMA16816(C[0][j], a0.x, a1.x, a0.y, a1.y, h.z, h.w);  // hi*lo
            MMA16816(C[0][j], a0.z, a1.z, a0.w, a1.w, h.x, h.y);  // lo*hi
            MMA16816(C[1][j], a2.x, a3.x, a2.y, a3.y, h.x, h.y);  // gates 2,3
            MMA16816(C[1][j], a2.x, a3.x, a2.y, a3.y, h.z, h.w);
            MMA16816(C[1][j], a2.z, a3.z, a2.w, a3.w, h.x, h.y);
        }
    }
}

// store / add C fragments into gates smem [r_local 32][row 128]; r_local = q*8 + unit
__device__ __forceinline__ void storeC(float C[2][4][4], float (*gs)[132])
{
    const int lane = threadIdx.x & 31;
    const int w4 = (threadIdx.x >> 5) & 3;
    const int g = lane >> 2, tg = lane & 3;
#pragma unroll
    for (int j = 0; j < 4; j++) {
        const int cb = w4 * 32 + j * 8 + 2 * tg;
#pragma unroll
        for (int m = 0; m < 2; m++) {
            gs[16 * m + g][cb]         = C[m][j][0];
            gs[16 * m + g][cb + 1]     = C[m][j][1];
            gs[16 * m + g + 8][cb]     = C[m][j][2];
            gs[16 * m + g + 8][cb + 1] = C[m][j][3];
        }
    }
}
__device__ __forceinline__ void addC(float C[2][4][4], float (*gs)[132])
{
    const int lane = threadIdx.x & 31;
    const int w4 = (threadIdx.x >> 5) & 3;
    const int g = lane >> 2, tg = lane & 3;
#pragma unroll
    for (int j = 0; j < 4; j++) {
        const int cb = w4 * 32 + j * 8 + 2 * tg;
#pragma unroll
        for (int m = 0; m < 2; m++) {
            gs[16 * m + g][cb]         += C[m][j][0];
            gs[16 * m + g][cb + 1]     += C[m][j][1];
            gs[16 * m + g + 8][cb]     += C[m][j][2];
            gs[16 * m + g + 8][cb + 1] += C[m][j][3];
        }
    }
}

// reduce 4 kg partials into 2 buffers (kg0/1 store, kg2/3 add; same thread ownership)
__device__ __forceinline__ void reduce4(float C[2][4][4], float (*gs01)[132],
                                        float (*gs23)[132], int kg)
{
    if (kg == 0) storeC(C, gs01);
    if (kg == 1) storeC(C, gs23);
    __syncthreads();
    if (kg == 2) addC(C, gs01);
    if (kg == 3) addC(C, gs23);
    __syncthreads();
}

#define ZERO_C(C) do { \
    _Pragma("unroll") for (int _m = 0; _m < 2; _m++) \
    _Pragma("unroll") for (int _j = 0; _j < 4; _j++) \
    _Pragma("unroll") for (int _k = 0; _k < 4; _k++) (C)[_m][_j][_k] = 0.f; } while (0)

// ---------------- bf16 MMA hoist GEMM: xg[t-slab] = W @ Sact[t-slab]^T ----------------
__global__ void __launch_bounds__(256, 2) hoist_mma(int wslot)
{
    __shared__ float gs[32][132];
    const int u0 = blockIdx.x * 8;
    const int t = blockIdx.y;
    const int tid = threadIdx.x;
    const int kg = tid >> 7;   // 0..1

    float C[2][4][4];
    ZERO_C(C);
    accum_m32(g_w4 + (size_t)wslot * WREC, g_s4 + (size_t)t * HREC, C, u0, kg, 32);
    if (kg == 0) storeC(C, gs);
    __syncthreads();
    if (kg == 1) addC(C, gs);
    __syncthreads();

#pragma unroll
    for (int pass = 0; pass < 16; pass++) {
        const int idx = pass * 256 + tid;
        const int b = idx & 127, r = idx >> 7;       // r = q*8 + uo
        g_xg[XG(t, r >> 3, u0 + (r & 7), b)] = gs[r][b];
    }
}

// ---------------- persistent encoder layer ----------------
__global__ void __launch_bounds__(NTHR, 1) enc_layer_kernel(
    int wslot, int dslot,
    const float* __restrict__ bih, const float* __restrict__ bhh,
    int write_seq)
{
    __shared__ float gs01[32][132];
    __shared__ float gs23[32][132];
    __shared__ float bias_s[32];
    const int tid = threadIdx.x;
    const int u0 = blockIdx.x * 8;
    const int kg = tid >> 7;        // 0..3 (also epilogue unit-pair index)
    const int be = tid & 127;
    const uint4* W4 = g_w4 + (size_t)wslot * WREC;

    if (tid < 32) {
        const int q = tid >> 3, uu = u0 + (tid & 7);
        bias_s[tid] = bih[(q << 10) + uu] + bhh[(q << 10) + uu];
    }
    __syncthreads();

    float cl[2] = {0.f, 0.f}, hl[2] = {0.f, 0.f};

#pragma unroll 1
    for (int t = 0; t < TDIM; t++) {
        float C[2][4][4];
        ZERO_C(C);
        const uint4* H = t ? g_eh4[t & 1] : g_z4;
        accum_m32(W4, H, C, u0, kg, 16);
        reduce4(C, gs01, gs23, kg);

        const int wp = (t + 1) & 1;
#pragma unroll
        for (int cc = 0; cc < 2; cc++) {
            const int j = kg + 4 * cc;
            const int ue = u0 + j;
            float ip = gs01[j][be]      + gs23[j][be]      + g_xg[XG(t, 0, ue, be)] + bias_s[j];
            float fp = gs01[8 + j][be]  + gs23[8 + j][be]  + g_xg[XG(t, 1, ue, be)] + bias_s[8 + j];
            float gp = gs01[16 + j][be] + gs23[16 + j][be] + g_xg[XG(t, 2, ue, be)] + bias_s[16 + j];
            float op = gs01[24 + j][be] + gs23[24 + j][be] + g_xg[XG(t, 3, ue, be)] + bias_s[24 + j];
            float cn = sigm(fp) * cl[cc] + sigm(ip) * tanhf(gp);
            float hn = sigm(op) * tanhf(cn);
            cl[cc] = cn; hl[cc] = hn;
            put_h(g_eh4[wp], be, ue, hn);
            if (write_seq)
                put_h(g_s4 + (size_t)t * HREC, be, ue, hn);
        }
        gsync();
    }
    // export final states for the decoder
#pragma unroll
    for (int cc = 0; cc < 2; cc++) {
        const int ue = u0 + kg + 4 * cc;
        g_cT[dslot * BH + be * HDIM + ue] = cl[cc];
        put_h(&g_dh4[0][dslot][0], be, ue, hl[cc]);
    }
}

// ---------------- persistent decoder (head folded into cell phases) ----------------
__global__ void __launch_bounds__(NTHR, 1) dec_kernel(
    const float* __restrict__ dWih0,
    const float* __restrict__ dbih0, const float* __restrict__ dbhh0,
    const float* __restrict__ dbih,  const float* __restrict__ dbhh,
    const float* __restrict__ Wu,    const float* __restrict__ bu,
    const float* __restrict__ y,     const int* __restrict__ force,
    float* __restrict__ out)
{
    __shared__ float gs01[32][132];
    __shared__ float gs23[32][132];
    __shared__ float b0_s[32], b1_s[32], b2_s[32], wc0_s[32];
    const int tid = threadIdx.x;
    const int u0 = blockIdx.x * 8;
    const int kg = tid >> 7;
    const int be = tid & 127;
    const float bu0 = bu[0];

    if (tid < 32) {
        const int q = tid >> 3;
        const int g = (q << 10) + u0 + (tid & 7);
        b0_s[tid]  = dbih0[g] + dbhh0[g];
        b1_s[tid]  = dbih[g] + dbhh[g];
        b2_s[tid]  = dbih[GDIM + g] + dbhh[GDIM + g];
        wc0_s[tid] = dWih0[g];
    }
    float c0[2], c1[2], c2[2];
#pragma unroll
    for (int cc = 0; cc < 2; cc++) {
        const int ue = u0 + kg + 4 * cc;
        c0[cc] = g_cT[0 * BH + be * HDIM + ue];
        c1[cc] = g_cT[1 * BH + be * HDIM + ue];
        c2[cc] = g_cT[2 * BH + be * HDIM + ue];
    }
    if (blockIdx.x == 0) {
        if (tid < 128) out[(size_t)tid * TDIM] = 0.f;        // output[:,0] = 0
        if (tid < 256) __stcg(&g_hacc[tid >> 7][tid & 127], 0.f);
    }
    __syncthreads();

#pragma unroll 1
    for (int s = 0; s < TDIM - 1; s++) {
        const int p = s & 1;
        float C[2][4][4];

        // ----- layer 0: gates = h0 @ Whh0^T (+ xfeed*Wih0 + b) -----
        ZERO_C(C);
        accum_m32(g_w4 + (size_t)W_DWH0 * WREC, &g_dh4[p][0][0], C, u0, kg, 16);
        reduce4(C, gs01, gs23, kg);
        {
            float xf;
            if (s == 0) {
                xf = y[(size_t)be * TDIM];
            } else {
                float prev = __ldcg(&g_hacc[(s - 1) & 1][be]) + bu0;
                xf = (force[s - 1] > 0) ? y[(size_t)be * TDIM + s] : prev;
                if (blockIdx.x == 0 && tid < 128)
                    out[(size_t)be * TDIM + s] = prev;
            }
#pragma unroll
            for (int cc = 0; cc < 2; cc++) {
                const int j = kg + 4 * cc;
                const int ue = u0 + j;
                float ip = gs01[j][be]      + gs23[j][be]      + xf * wc0_s[j]      + b0_s[j];
                float fp = gs01[8 + j][be]  + gs23[8 + j][be]  + xf * wc0_s[8 + j]  + b0_s[8 + j];
                float gp = gs01[16 + j][be] + gs23[16 + j][be] + xf * wc0_s[16 + j] + b0_s[16 + j];
                float op = gs01[24 + j][be] + gs23[24 + j][be] + xf * wc0_s[24 + j] + b0_s[24 + j];
                float cn = sigm(fp) * c0[cc] + sigm(ip) * tanhf(gp);
                float hn = sigm(op) * tanhf(cn);
                c0[cc] = cn;
                put_h(&g_dh4[p ^ 1][0][0], be, ue, hn);
            }
        }
        gsync();

        // ----- layer 1: gates = h0_new @ Wih1^T + h1 @ Whh1^T -----
        ZERO_C(C);
        accum_m32(g_w4 + (size_t)W_DWI1 * WREC, &g_dh4[p ^ 1][0][0], C, u0, kg, 16);
        accum_m32(g_w4 + (size_t)W_DWH1 * WREC, &g_dh4[p][1][0], C, u0, kg, 16);
        reduce4(C, gs01, gs23, kg);
        if (s >= 1 && blockIdx.x == 0 && tid < 128)
            __stcg(&g_hacc[(s - 1) & 1][tid], 0.f);          // reset consumed head buffer
#pragma unroll
        for (int cc = 0; cc < 2; cc++) {
            const int j = kg + 4 * cc;
            const int ue = u0 + j;
            float ip = gs01[j][be]      + gs23[j][be]      + b1_s[j];
            float fp = gs01[8 + j][be]  + gs23[8 + j][be]  + b1_s[8 + j];
            float gp = gs01[16 + j][be] + gs23[16 + j][be] + b1_s[16 + j];
            float op = gs01[24 + j][be] + gs23[24 + j][be] + b1_s[24 + j];
            float cn = sigm(fp) * c1[cc] + sigm(ip) * tanhf(gp);
            float hn = sigm(op) * tanhf(cn);
            c1[cc] = cn;
            put_h(&g_dh4[p ^ 1][1][0], be, ue, hn);
        }
        gsync();

        // ----- layer 2 (+ head partials) -----
        ZERO_C(C);
        accum_m32(g_w4 + (size_t)W_DWI2 * WREC, &g_dh4[p ^ 1][1][0], C, u0, kg, 16);
        accum_m32(g_w4 + (size_t)W_DWH2 * WREC, &g_dh4[p][2][0], C, u0, kg, 16);
        reduce4(C, gs01, gs23, kg);
        {
            float part = 0.f;
#pragma unroll
            for (int cc = 0; cc < 2; cc++) {
                const int j = kg + 4 * cc;
                const int ue = u0 + j;
                float ip = gs01[j][be]      + gs23[j][be]      + b2_s[j];
                float fp = gs01[8 + j][be]  + gs23[8 + j][be]  + b2_s[8 + j];
                float gp = gs01[16 + j][be] + gs23[16 + j][be] + b2_s[16 + j];
                float op = gs01[24 + j][be] + gs23[24 + j][be] + b2_s[24 + j];
                float cn = sigm(fp) * c2[cc] + sigm(ip) * tanhf(gp);
                float hn = sigm(op) * tanhf(cn);
                c2[cc] = cn;
                part += hn * Wu[ue];
                put_h(&g_dh4[p ^ 1][2][0], be, ue, hn);
            }
            atomicAdd(&g_hacc[s & 1][be], part);
        }
        gsync();
    }
    // tail: final output position T-1 from step T-2's head sum
    if (blockIdx.x == 0 && tid < 128)
        out[(size_t)tid * TDIM + (TDIM - 1)] = __ldcg(&g_hacc[(TDIM - 2) & 1][tid]) + bu0;
}

// ---------------- fp32 NT GEMM for the tiny K=32 layer-0 hoist ----------------
// writes xg in [t][q][u][b] layout
__global__ void __launch_bounds__(256) gemm_hoist(
    const float* __restrict__ A, const float* __restrict__ B, int K)
{
    __shared__ float As[16][68];
    __shared__ float Bs[16][68];
    const int tid = threadIdx.x;
    const int tx = tid & 15, ty = tid >> 4;
    const int m0 = blockIdx.y * 64, n0 = blockIdx.x * 64;
    const int lr = tid >> 2;
    const int lc = (tid & 3) * 4;

    float acc[4][4];
#pragma unroll
    for (int i = 0; i < 4; i++)
#pragma unroll
        for (int jj = 0; jj < 4; jj++) acc[i][jj] = 0.f;

#pragma unroll 1
    for (int k0 = 0; k0 < K; k0 += 16) {
        float4 av = *(const float4*)&A[(size_t)(m0 + lr) * K + k0 + lc];
        float4 bv = *(const float4*)&B[(size_t)(n0 + lr) * K + k0 + lc];
        __syncthreads();
        As[lc + 0][lr] = av.x; As[lc + 1][lr] = av.y; As[lc + 2][lr] = av.z; As[lc + 3][lr] = av.w;
        Bs[lc + 0][lr] = bv.x; Bs[lc + 1][lr] = bv.y; Bs[lc + 2][lr] = bv.z; Bs[lc + 3][lr] = bv.w;
        __syncthreads();
#pragma unroll
        for (int k = 0; k < 16; k++) {
            float4 a = *(const float4*)&As[k][ty * 4];
            float4 b = *(const float4*)&Bs[k][tx * 4];
            acc[0][0] += a.x * b.x; acc[0][1] += a.x * b.y; acc[0][2] += a.x * b.z; acc[0][3] += a.x * b.w;
            acc[1][0] += a.y * b.x; acc[1][1] += a.y * b.y; acc[1][2] += a.y * b.z; acc[1][3] += a.y * b.w;
            acc[2][0] += a.z * b.x; acc[2][1] += a.z * b.y; acc[2][2] += a.z * b.z; acc[2][3] += a.z * b.w;
            acc[3][0] += a.w * b.x; acc[3][1] += a.w * b.y; acc[3][2] += a.w * b.z; acc[3][3] += a.w * b.w;
        }
    }
#pragma unroll
    for (int i = 0; i < 4; i++) {
        const int m = m0 + ty * 4 + i;               // m = b*TDIM + t
        const int bb = m >> 9, t = m & 511;
#pragma unroll
        for (int jj = 0; jj < 4; jj++) {
            const int n = n0 + tx * 4 + jj;          // n = q*1024 + u
            g_xg[XG(t, n >> 10, n & 1023, bb)] = acc[i][jj];
        }
    }
}

// ---------------- host orchestration: 8 graph nodes ----------------
extern "C" void kernel_launch(void* const* d_in, const int* in_sizes, int n_in,
                              void* d_out, int out_size)
{
    (void)in_sizes; (void)n_in; (void)out_size;

    const float* x     = (const float*)d_in[0];
    const float* y     = (const float*)d_in[1];
    const int*   force = (const int*)  d_in[2];
    const float* eWih0 = (const float*)d_in[3];
    const float* eWhh0 = (const float*)d_in[4];
    const float* ebih0 = (const float*)d_in[5];
    const float* ebhh0 = (const float*)d_in[6];
    const float* eWih  = (const float*)d_in[7];
    const float* eWhh  = (const float*)d_in[8];
    const float* ebih  = (const float*)d_in[9];
    const float* ebhh  = (const float*)d_in[10];
    const float* dWih0 = (const float*)d_in[11];
    const float* dWhh0 = (const float*)d_in[12];
    const float* dbih0 = (const float*)d_in[13];
    const float* dbhh0 = (const float*)d_in[14];
    const float* dWih  = (const float*)d_in[15];
    const float* dWhh  = (const float*)d_in[16];
    const float* dbih  = (const float*)d_in[17];
    const float* dbhh  = (const float*)d_in[18];
    const float* Wu    = (const float*)d_in[19];
    const float* bu    = (const float*)d_in[20];
    float* out = (float*)d_out;

    const size_t WSTRIDE = (size_t)GDIM * HDIM;
    const dim3 gBig(GDIM / 64, (BDIM * TDIM) / 64);
    const dim3 gHoist(HDIM / 8, TDIM);

    // split all recurrent + hoist weights into packed bf16 hi/lo records
    prep_w<<<2048, 256>>>(eWhh0, eWhh, eWhh + WSTRIDE,
                          dWhh0, dWih, dWih + WSTRIDE,
                          dWhh, dWhh + WSTRIDE,
                          eWih, eWih + WSTRIDE);

    // encoder layer 0 (input hoist is tiny K=32 fp32 GEMM)
    gemm_hoist<<<gBig, 256>>>(x, eWih0, IDIM);
    enc_layer_kernel<<<NBLK, NTHR>>>(W_EWH0, 0, ebih0, ebhh0, /*write_seq=*/1);
    // encoder layer 1
    hoist_mma<<<gHoist, 256>>>(W_HWI1);
    enc_layer_kernel<<<NBLK, NTHR>>>(W_EWH1, 1, ebih, ebhh, /*write_seq=*/1);
    // encoder layer 2
    hoist_mma<<<gHoist, 256>>>(W_HWI2);
    enc_layer_kernel<<<NBLK, NTHR>>>(W_EWH2, 2, ebih + GDIM, ebhh + GDIM, /*write_seq=*/0);

    // decoder (persistent, all 511 steps)
    dec_kernel<<<NBLK, NTHR>>>(dWih0, dbih0, dbhh0, dbih, dbhh,
                               Wu, bu, y, force, out);
}